// round 6
// baseline (speedup 1.0000x reference)
#include <cuda_runtime.h>
#include <math.h>
#include <stdint.h>

#define NTOK 4096
#define CDIM 768
#define NH   12
#define HD   64
#define FF   3072
#define QKVD 2304

// ---------------- scratch ----------------------------------------------------
__device__ float g_h[NTOK * CDIM];
__device__ float g_qkv[NTOK * QKVD];
__device__ float g_o[NTOK * CDIM];
__device__ float g_x1[NTOK * CDIM];
__device__ float g_fc1[NTOK * FF];

// ---------------- helpers ----------------------------------------------------
__device__ __forceinline__ uint32_t cvt_tf32(float f) {
    uint32_t r;
    asm("cvt.rna.tf32.f32 %0, %1;" : "=r"(r) : "f"(f));
    return r;
}
__device__ __forceinline__ void mma_tf32(float* d, const uint32_t* a, const uint32_t* b) {
    asm volatile(
        "mma.sync.aligned.m16n8k8.row.col.f32.tf32.tf32.f32 "
        "{%0,%1,%2,%3}, {%4,%5,%6,%7}, {%8,%9}, {%0,%1,%2,%3};\n"
        : "+f"(d[0]), "+f"(d[1]), "+f"(d[2]), "+f"(d[3])
        : "r"(a[0]), "r"(a[1]), "r"(a[2]), "r"(a[3]), "r"(b[0]), "r"(b[1]));
}

// 2^x on the FMA pipe (softmax args <= 0; clamp handles sentinels)
__device__ __forceinline__ float fexp2(float x) {
    x = fmaxf(x, -126.0f);
    int e = __float2int_rn(x);
    float f = x - (float)e;
    float p = fmaf(f, 0.00133336f, 0.00961813f);
    p = fmaf(f, p, 0.0555041f);
    p = fmaf(f, p, 0.2402265f);
    p = fmaf(f, p, 0.6931472f);
    p = fmaf(f, p, 1.0f);
    return __int_as_float((e + 127) << 23) * p;
}

// ---------------- LayerNorm --------------------------------------------------
__global__ __launch_bounds__(256) void ln_kernel(
    const float* __restrict__ x, const float* __restrict__ g,
    const float* __restrict__ b, float* __restrict__ out)
{
    const int row = blockIdx.x;
    const int tid = threadIdx.x;
    const float* xr = x + row * CDIM;
    float v[3];
    float s = 0.f;
#pragma unroll
    for (int i = 0; i < 3; i++) { v[i] = xr[tid + 256 * i]; s += v[i]; }

    __shared__ float sh[8];
#pragma unroll
    for (int o = 16; o > 0; o >>= 1) s += __shfl_xor_sync(0xffffffffu, s, o);
    if ((tid & 31) == 0) sh[tid >> 5] = s;
    __syncthreads();
    if (tid < 8) {
        s = sh[tid];
#pragma unroll
        for (int o = 4; o > 0; o >>= 1) s += __shfl_xor_sync(0xffu, s, o);
        if (tid == 0) sh[0] = s;
    }
    __syncthreads();
    const float mu = sh[0] * (1.0f / CDIM);
    __syncthreads();

    float s2 = 0.f;
#pragma unroll
    for (int i = 0; i < 3; i++) { float d = v[i] - mu; s2 += d * d; }
#pragma unroll
    for (int o = 16; o > 0; o >>= 1) s2 += __shfl_xor_sync(0xffffffffu, s2, o);
    if ((tid & 31) == 0) sh[tid >> 5] = s2;
    __syncthreads();
    if (tid < 8) {
        s2 = sh[tid];
#pragma unroll
        for (int o = 4; o > 0; o >>= 1) s2 += __shfl_xor_sync(0xffu, s2, o);
        if (tid == 0) sh[0] = s2;
    }
    __syncthreads();
    const float rstd = rsqrtf(sh[0] * (1.0f / CDIM) + 1e-5f);

    float* orow = out + row * CDIM;
#pragma unroll
    for (int i = 0; i < 3; i++) {
        int c = tid + 256 * i;
        orow[c] = (v[i] - mu) * rstd * g[c] + b[c];
    }
}

// ---------------- tf32 mma GEMM-NT 128x128 (for big-N GEMMs) ----------------
#define GSA 36
#define GSTAGE (2 * 128 * GSA)

template <bool HAS_BIAS, bool HAS_RES, bool DO_GELU>
__global__ __launch_bounds__(256) void gemm_mma(
    const float* __restrict__ A, const float* __restrict__ B,
    const float* __restrict__ bias, const float* __restrict__ res,
    float* __restrict__ C, int M, int Nc, int K)
{
    extern __shared__ float sm[];
    const int tid = threadIdx.x;
    const int lane = tid & 31;
    const int wid = tid >> 5;
    const int wm = (wid & 3) * 32;
    const int wn = (wid >> 2) * 64;
    const int m0 = blockIdx.y * 128;
    const int n0 = blockIdx.x * 128;
    const int r = lane >> 2;
    const int q = lane & 3;

    const int lrow = tid >> 1;
    const int lcol = (tid & 1) * 16;
    const float* Ag = A + (long)(m0 + lrow) * K + lcol;
    const float* Bg = B + (long)(n0 + lrow) * K + lcol;
    const int ktiles = K >> 5;

    float acc[2][8][4];
#pragma unroll
    for (int mt = 0; mt < 2; mt++)
#pragma unroll
        for (int nt = 0; nt < 8; nt++)
#pragma unroll
            for (int j = 0; j < 4; j++) acc[mt][nt][j] = 0.f;

    float4 ra[4], rb[4];
#pragma unroll
    for (int v = 0; v < 4; v++) {
        ra[v] = *(const float4*)(Ag + v * 4);
        rb[v] = *(const float4*)(Bg + v * 4);
    }
    {
        uint32_t* Au = (uint32_t*)sm;
        uint32_t* Bu = Au + 128 * GSA;
#pragma unroll
        for (int v = 0; v < 4; v++) {
            int off = lrow * GSA + lcol + v * 4;
            uint4 at = {cvt_tf32(ra[v].x), cvt_tf32(ra[v].y), cvt_tf32(ra[v].z), cvt_tf32(ra[v].w)};
            uint4 bt = {cvt_tf32(rb[v].x), cvt_tf32(rb[v].y), cvt_tf32(rb[v].z), cvt_tf32(rb[v].w)};
            *(uint4*)(Au + off) = at;
            *(uint4*)(Bu + off) = bt;
        }
    }
    if (ktiles > 1) {
#pragma unroll
        for (int v = 0; v < 4; v++) {
            ra[v] = *(const float4*)(Ag + 32 + v * 4);
            rb[v] = *(const float4*)(Bg + 32 + v * 4);
        }
    }
    __syncthreads();

    for (int kt = 0; kt < ktiles; kt++) {
        const int b = kt & 1;
        if (kt + 1 < ktiles) {
            uint32_t* Au = (uint32_t*)(sm + (b ^ 1) * GSTAGE);
            uint32_t* Bu = Au + 128 * GSA;
#pragma unroll
            for (int v = 0; v < 4; v++) {
                int off = lrow * GSA + lcol + v * 4;
                uint4 at = {cvt_tf32(ra[v].x), cvt_tf32(ra[v].y), cvt_tf32(ra[v].z), cvt_tf32(ra[v].w)};
                uint4 bt = {cvt_tf32(rb[v].x), cvt_tf32(rb[v].y), cvt_tf32(rb[v].z), cvt_tf32(rb[v].w)};
                *(uint4*)(Au + off) = at;
                *(uint4*)(Bu + off) = bt;
            }
            if (kt + 2 < ktiles) {
#pragma unroll
                for (int v = 0; v < 4; v++) {
                    ra[v] = *(const float4*)(Ag + (kt + 2) * 32 + v * 4);
                    rb[v] = *(const float4*)(Bg + (kt + 2) * 32 + v * 4);
                }
            }
        }
        {
            const uint32_t* Au = (const uint32_t*)(sm + b * GSTAGE);
            const uint32_t* Bu = Au + 128 * GSA;
#pragma unroll
            for (int kc = 0; kc < 4; kc++) {
                uint32_t af[2][4];
#pragma unroll
                for (int mt = 0; mt < 2; mt++) {
                    const uint32_t* base = Au + (wm + mt * 16 + r) * GSA + kc * 8 + q;
                    af[mt][0] = base[0];
                    af[mt][1] = base[8 * GSA];
                    af[mt][2] = base[4];
                    af[mt][3] = base[8 * GSA + 4];
                }
#pragma unroll
                for (int nt = 0; nt < 8; nt++) {
                    uint32_t bf[2];
                    const uint32_t* base = Bu + (wn + nt * 8 + r) * GSA + kc * 8 + q;
                    bf[0] = base[0];
                    bf[1] = base[4];
#pragma unroll
                    for (int mt = 0; mt < 2; mt++)
                        mma_tf32(acc[mt][nt], af[mt], bf);
                }
            }
        }
        __syncthreads();
    }

#pragma unroll
    for (int mt = 0; mt < 2; mt++) {
#pragma unroll
        for (int rr = 0; rr < 2; rr++) {
            const int m = m0 + wm + mt * 16 + r + rr * 8;
            float* crow = C + (long)m * Nc;
            const float* rrow = HAS_RES ? (res + (long)m * Nc) : nullptr;
#pragma unroll
            for (int nt = 0; nt < 8; nt++) {
                const int n = n0 + wn + nt * 8 + 2 * q;
                float v0 = acc[mt][nt][rr * 2 + 0];
                float v1 = acc[mt][nt][rr * 2 + 1];
                if (HAS_BIAS) { v0 += bias[n]; v1 += bias[n + 1]; }
                if (DO_GELU) {
                    v0 = 0.5f * v0 * (1.0f + erff(v0 * 0.70710678118654752f));
                    v1 = 0.5f * v1 * (1.0f + erff(v1 * 0.70710678118654752f));
                }
                if (HAS_RES) { v0 += rrow[n]; v1 += rrow[n + 1]; }
                float2 w = {v0, v1};
                *(float2*)(crow + n) = w;
            }
        }
    }
}

// ---------------- tf32 mma GEMM-NT 64x128 (for N=768 GEMMs) ------------------
// 128 threads, 4 warps (2M x 2N), warp tile 32x64, 4 CTAs/SM.
#define G64STAGE ((64 + 128) * GSA)   // floats per stage

template <bool HAS_BIAS, bool HAS_RES, bool DO_GELU>
__global__ __launch_bounds__(128, 4) void gemm64(
    const float* __restrict__ A, const float* __restrict__ B,
    const float* __restrict__ bias, const float* __restrict__ res,
    float* __restrict__ C, int M, int Nc, int K)
{
    extern __shared__ float sm[];
    const int tid = threadIdx.x;
    const int lane = tid & 31;
    const int wid = tid >> 5;
    const int wm = (wid & 1) * 32;
    const int wn = (wid >> 1) * 64;
    const int m0 = blockIdx.y * 64;
    const int n0 = blockIdx.x * 128;
    const int r = lane >> 2;
    const int q = lane & 3;

    const int lrow = tid >> 1;          // 0..63
    const int lcol = (tid & 1) * 16;
    const float* Ag  = A + (long)(m0 + lrow) * K + lcol;
    const float* Bg0 = B + (long)(n0 + lrow) * K + lcol;
    const float* Bg1 = Bg0 + (long)64 * K;
    const int ktiles = K >> 5;

    float acc[2][8][4];
#pragma unroll
    for (int mt = 0; mt < 2; mt++)
#pragma unroll
        for (int nt = 0; nt < 8; nt++)
#pragma unroll
            for (int j = 0; j < 4; j++) acc[mt][nt][j] = 0.f;

    float4 ra[4], rb0[4], rb1[4];
#pragma unroll
    for (int v = 0; v < 4; v++) {
        ra[v]  = *(const float4*)(Ag + v * 4);
        rb0[v] = *(const float4*)(Bg0 + v * 4);
        rb1[v] = *(const float4*)(Bg1 + v * 4);
    }
    {
        uint32_t* Au = (uint32_t*)sm;
        uint32_t* Bu = Au + 64 * GSA;
#pragma unroll
        for (int v = 0; v < 4; v++) {
            int off = lrow * GSA + lcol + v * 4;
            uint4 at = {cvt_tf32(ra[v].x), cvt_tf32(ra[v].y), cvt_tf32(ra[v].z), cvt_tf32(ra[v].w)};
            uint4 b0 = {cvt_tf32(rb0[v].x), cvt_tf32(rb0[v].y), cvt_tf32(rb0[v].z), cvt_tf32(rb0[v].w)};
            uint4 b1 = {cvt_tf32(rb1[v].x), cvt_tf32(rb1[v].y), cvt_tf32(rb1[v].z), cvt_tf32(rb1[v].w)};
            *(uint4*)(Au + off) = at;
            *(uint4*)(Bu + off) = b0;
            *(uint4*)(Bu + 64 * GSA + off) = b1;
        }
    }
    if (ktiles > 1) {
#pragma unroll
        for (int v = 0; v < 4; v++) {
            ra[v]  = *(const float4*)(Ag + 32 + v * 4);
            rb0[v] = *(const float4*)(Bg0 + 32 + v * 4);
            rb1[v] = *(const float4*)(Bg1 + 32 + v * 4);
        }
    }
    __syncthreads();

    for (int kt = 0; kt < ktiles; kt++) {
        const int b = kt & 1;
        if (kt + 1 < ktiles) {
            uint32_t* Au = (uint32_t*)(sm + (b ^ 1) * G64STAGE);
            uint32_t* Bu = Au + 64 * GSA;
#pragma unroll
            for (int v = 0; v < 4; v++) {
                int off = lrow * GSA + lcol + v * 4;
                uint4 at = {cvt_tf32(ra[v].x), cvt_tf32(ra[v].y), cvt_tf32(ra[v].z), cvt_tf32(ra[v].w)};
                uint4 b0 = {cvt_tf32(rb0[v].x), cvt_tf32(rb0[v].y), cvt_tf32(rb0[v].z), cvt_tf32(rb0[v].w)};
                uint4 b1 = {cvt_tf32(rb1[v].x), cvt_tf32(rb1[v].y), cvt_tf32(rb1[v].z), cvt_tf32(rb1[v].w)};
                *(uint4*)(Au + off) = at;
                *(uint4*)(Bu + off) = b0;
                *(uint4*)(Bu + 64 * GSA + off) = b1;
            }
            if (kt + 2 < ktiles) {
#pragma unroll
                for (int v = 0; v < 4; v++) {
                    ra[v]  = *(const float4*)(Ag + (kt + 2) * 32 + v * 4);
                    rb0[v] = *(const float4*)(Bg0 + (kt + 2) * 32 + v * 4);
                    rb1[v] = *(const float4*)(Bg1 + (kt + 2) * 32 + v * 4);
                }
            }
        }
        {
            const uint32_t* Au = (const uint32_t*)(sm + b * G64STAGE);
            const uint32_t* Bu = Au + 64 * GSA;
#pragma unroll
            for (int kc = 0; kc < 4; kc++) {
                uint32_t af[2][4];
#pragma unroll
                for (int mt = 0; mt < 2; mt++) {
                    const uint32_t* base = Au + (wm + mt * 16 + r) * GSA + kc * 8 + q;
                    af[mt][0] = base[0];
                    af[mt][1] = base[8 * GSA];
                    af[mt][2] = base[4];
                    af[mt][3] = base[8 * GSA + 4];
                }
#pragma unroll
                for (int nt = 0; nt < 8; nt++) {
                    uint32_t bf[2];
                    const uint32_t* base = Bu + (wn + nt * 8 + r) * GSA + kc * 8 + q;
                    bf[0] = base[0];
                    bf[1] = base[4];
#pragma unroll
                    for (int mt = 0; mt < 2; mt++)
                        mma_tf32(acc[mt][nt], af[mt], bf);
                }
            }
        }
        __syncthreads();
    }

#pragma unroll
    for (int mt = 0; mt < 2; mt++) {
#pragma unroll
        for (int rr = 0; rr < 2; rr++) {
            const int m = m0 + wm + mt * 16 + r + rr * 8;
            float* crow = C + (long)m * Nc;
            const float* rrow = HAS_RES ? (res + (long)m * Nc) : nullptr;
#pragma unroll
            for (int nt = 0; nt < 8; nt++) {
                const int n = n0 + wn + nt * 8 + 2 * q;
                float v0 = acc[mt][nt][rr * 2 + 0];
                float v1 = acc[mt][nt][rr * 2 + 1];
                if (HAS_BIAS) { v0 += bias[n]; v1 += bias[n + 1]; }
                if (DO_GELU) {
                    v0 = 0.5f * v0 * (1.0f + erff(v0 * 0.70710678118654752f));
                    v1 = 0.5f * v1 * (1.0f + erff(v1 * 0.70710678118654752f));
                }
                if (HAS_RES) { v0 += rrow[n]; v1 += rrow[n + 1]; }
                float2 w = {v0, v1};
                *(float2*)(crow + n) = w;
            }
        }
    }
}

// ---------------- RoPE -------------------------------------------------------
__global__ __launch_bounds__(256) void rope_kernel(
    float* __restrict__ qkv, const float* __restrict__ cos_t,
    const float* __restrict__ sin_t)
{
    int idx = blockIdx.x * blockDim.x + threadIdx.x;
    if (idx >= NTOK * NH * (HD / 2)) return;
    const int i = idx & 31;
    const int h = (idx >> 5) % NH;
    const int n = idx / (NH * (HD / 2));
    const float c = cos_t[n * 32 + i];
    const float s = sin_t[n * 32 + i];
#pragma unroll
    for (int sel = 0; sel < 2; sel++) {
        float* p = qkv + (long)n * QKVD + sel * CDIM + h * HD + 2 * i;
        float t0 = p[0], t1 = p[1];
        p[0] = t0 * c - t1 * s;
        p[1] = t0 * s + t1 * c;
    }
}

// ---------------- flash attention, 64-row CTAs -------------------------------
// CTA: 64 q-rows x one head; 4 warps, warp = 16 q-rows. Key tiles of 64.
// smem: Ks[key][d] 64x68, Vs[d][key] 64x68 (transposed), Qs/Ps[64][68].
// 4 CTAs/SM: small work quanta minimize tail-wave waste.
__global__ __launch_bounds__(128, 4) void attn_mma(
    const float* __restrict__ qkv, float* __restrict__ out)
{
    extern __shared__ float sm[];
    float* Ks = sm;                 // [key][d]
    float* Vs = sm + 64 * 68;       // [d][key] transposed
    float* Qs = sm + 2 * 64 * 68;   // [64][68]; later per-warp P tiles

    const int tid = threadIdx.x;
    const int lane = tid & 31;
    const int wid = tid >> 5;       // 0..3
    const int h = blockIdx.y;
    const int q0 = blockIdx.x * 64;
    const int r = lane >> 2;
    const int q = lane & 3;
    const float QSCALE = 0.125f * 1.4426950408889634f;   // scale * log2e

    // stage Q (scaled, tf32): row = tid>>1 (0..63), c0 = (tid&1)*32
    {
        const int row = tid >> 1;
        const int c0 = (tid & 1) * 32;
        const float* qp = qkv + (long)(q0 + row) * QKVD + h * HD + c0;
        uint32_t* dst = (uint32_t*)(Qs + row * 68 + c0);
#pragma unroll
        for (int v = 0; v < 8; v++) {
            float4 t = *(const float4*)(qp + v * 4);
            dst[v * 4 + 0] = cvt_tf32(t.x * QSCALE);
            dst[v * 4 + 1] = cvt_tf32(t.y * QSCALE);
            dst[v * 4 + 2] = cvt_tf32(t.z * QSCALE);
            dst[v * 4 + 3] = cvt_tf32(t.w * QSCALE);
        }
    }
    __syncthreads();

    // Q a-fragments (per warp: 16 rows x 64 d, 8 k-steps)
    uint32_t qf[8][4];
    {
        const uint32_t* Qu = (const uint32_t*)(Qs + wid * 16 * 68);
#pragma unroll
        for (int kc = 0; kc < 8; kc++) {
            const uint32_t* b = Qu + r * 68 + kc * 8 + q;
            qf[kc][0] = b[0];
            qf[kc][1] = b[8 * 68];
            qf[kc][2] = b[4];
            qf[kc][3] = b[8 * 68 + 4];
        }
    }
    __syncthreads();   // Qs now reusable as P

    float m0v = -1e30f, m1v = -1e30f, l0 = 0.f, l1 = 0.f;
    float of[8][4];
#pragma unroll
    for (int nt = 0; nt < 8; nt++)
#pragma unroll
        for (int j = 0; j < 4; j++) of[nt][j] = 0.f;

    uint32_t* Pu = (uint32_t*)(Qs + wid * 16 * 68);

    for (int kt = 0; kt < NTOK / 64; kt++) {
        // stage K [key][d], V [d][key]: kr = tid&63, half covers 32 cols
        {
            const int kr = tid & 63;
            const int c0 = (tid >> 6) * 32;
            const float* kp = qkv + (long)(kt * 64 + kr) * QKVD + CDIM + h * HD + c0;
            const float* vp = kp + CDIM;
            uint32_t* kd = (uint32_t*)(Ks + kr * 68 + c0);
            uint32_t* vd = (uint32_t*)Vs;
#pragma unroll
            for (int v = 0; v < 8; v++) {
                float4 kk = *(const float4*)(kp + v * 4);
                kd[v * 4 + 0] = cvt_tf32(kk.x); kd[v * 4 + 1] = cvt_tf32(kk.y);
                kd[v * 4 + 2] = cvt_tf32(kk.z); kd[v * 4 + 3] = cvt_tf32(kk.w);
                float4 vvv = *(const float4*)(vp + v * 4);
                vd[(c0 + v * 4 + 0) * 68 + kr] = cvt_tf32(vvv.x);
                vd[(c0 + v * 4 + 1) * 68 + kr] = cvt_tf32(vvv.y);
                vd[(c0 + v * 4 + 2) * 68 + kr] = cvt_tf32(vvv.z);
                vd[(c0 + v * 4 + 3) * 68 + kr] = cvt_tf32(vvv.w);
            }
        }
        __syncthreads();

        // S = Q K^T : warp 16x64 tile (log2 domain)
        float sf[8][4];
#pragma unroll
        for (int nt = 0; nt < 8; nt++)
#pragma unroll
            for (int j = 0; j < 4; j++) sf[nt][j] = 0.f;
        {
            const uint32_t* Ku = (const uint32_t*)Ks;
#pragma unroll
            for (int kc = 0; kc < 8; kc++) {
#pragma unroll
                for (int nt = 0; nt < 8; nt++) {
                    uint32_t bf[2];
                    const uint32_t* bb = Ku + (nt * 8 + r) * 68 + kc * 8 + q;
                    bf[0] = bb[0];
                    bf[1] = bb[4];
                    mma_tf32(sf[nt], qf[kc], bf);
                }
            }
        }

        // online softmax
        float rm0 = -1e30f, rm1 = -1e30f;
#pragma unroll
        for (int nt = 0; nt < 8; nt++) {
            rm0 = fmaxf(rm0, fmaxf(sf[nt][0], sf[nt][1]));
            rm1 = fmaxf(rm1, fmaxf(sf[nt][2], sf[nt][3]));
        }
        rm0 = fmaxf(rm0, __shfl_xor_sync(0xffffffffu, rm0, 1));
        rm0 = fmaxf(rm0, __shfl_xor_sync(0xffffffffu, rm0, 2));
        rm1 = fmaxf(rm1, __shfl_xor_sync(0xffffffffu, rm1, 1));
        rm1 = fmaxf(rm1, __shfl_xor_sync(0xffffffffu, rm1, 2));
        const float mn0 = fmaxf(m0v, rm0);
        const float mn1 = fmaxf(m1v, rm1);
        const float corr0 = fexp2(m0v - mn0);
        const float corr1 = fexp2(m1v - mn1);
        float rs0 = 0.f, rs1 = 0.f;
#pragma unroll
        for (int nt = 0; nt < 8; nt++) {
            float p0 = fexp2(sf[nt][0] - mn0);
            float p1 = fexp2(sf[nt][1] - mn0);
            float p2 = fexp2(sf[nt][2] - mn1);
            float p3 = fexp2(sf[nt][3] - mn1);
            rs0 += p0 + p1;
            rs1 += p2 + p3;
            uint2 w0 = {cvt_tf32(p0), cvt_tf32(p1)};
            uint2 w1 = {cvt_tf32(p2), cvt_tf32(p3)};
            *(uint2*)(Pu + r * 68 + nt * 8 + 2 * q) = w0;
            *(uint2*)(Pu + (r + 8) * 68 + nt * 8 + 2 * q) = w1;
        }
        rs0 += __shfl_xor_sync(0xffffffffu, rs0, 1);
        rs0 += __shfl_xor_sync(0xffffffffu, rs0, 2);
        rs1 += __shfl_xor_sync(0xffffffffu, rs1, 1);
        rs1 += __shfl_xor_sync(0xffffffffu, rs1, 2);
        l0 = l0 * corr0 + rs0;
        l1 = l1 * corr1 + rs1;
        m0v = mn0;
        m1v = mn1;
#pragma unroll
        for (int nt = 0; nt < 8; nt++) {
            of[nt][0] *= corr0; of[nt][1] *= corr0;
            of[nt][2] *= corr1; of[nt][3] *= corr1;
        }
        __syncwarp();

        // O += P V (V transposed -> conflict-free B frags)
        {
            const uint32_t* Vu = (const uint32_t*)Vs;
#pragma unroll
            for (int kc = 0; kc < 8; kc++) {
                uint32_t af[4];
                const uint32_t* ab = Pu + r * 68 + kc * 8 + q;
                af[0] = ab[0];
                af[1] = ab[8 * 68];
                af[2] = ab[4];
                af[3] = ab[8 * 68 + 4];
#pragma unroll
                for (int nt = 0; nt < 8; nt++) {
                    uint32_t bf[2];
                    const uint32_t* bb = Vu + (nt * 8 + r) * 68 + kc * 8 + q;
                    bf[0] = bb[0];
                    bf[1] = bb[4];
                    mma_tf32(of[nt], af, bf);
                }
            }
        }
        __syncthreads();
    }

    // normalize + store
    const float inv0 = 1.0f / l0;
    const float inv1 = 1.0f / l1;
    const int row0 = q0 + wid * 16 + r;
#pragma unroll
    for (int nt = 0; nt < 8; nt++) {
        const int col = h * HD + nt * 8 + 2 * q;
        float2 w0 = {of[nt][0] * inv0, of[nt][1] * inv0};
        float2 w1 = {of[nt][2] * inv1, of[nt][3] * inv1};
        *(float2*)(out + (long)row0 * CDIM + col) = w0;
        *(float2*)(out + (long)(row0 + 8) * CDIM + col) = w1;
    }
}

// ---------------- launch -----------------------------------------------------
extern "C" void kernel_launch(void* const* d_in, const int* in_sizes, int n_in,
                              void* d_out, int out_size)
{
    const float* x      = (const float*)d_in[0];
    const float* cos_t  = (const float*)d_in[1];
    const float* sin_t  = (const float*)d_in[2];
    const float* w_qkv  = (const float*)d_in[3];
    const float* w_proj = (const float*)d_in[4];
    const float* b_proj = (const float*)d_in[5];
    const float* g1     = (const float*)d_in[6];
    const float* beta1  = (const float*)d_in[7];
    const float* g2     = (const float*)d_in[8];
    const float* beta2  = (const float*)d_in[9];
    const float* w_fc1  = (const float*)d_in[10];
    const float* b_fc1  = (const float*)d_in[11];
    const float* w_fc2  = (const float*)d_in[12];
    const float* b_fc2  = (const float*)d_in[13];
    float* out = (float*)d_out;

    float *h, *qkv, *o, *x1, *fc1;
    cudaGetSymbolAddress((void**)&h,   g_h);
    cudaGetSymbolAddress((void**)&qkv, g_qkv);
    cudaGetSymbolAddress((void**)&o,   g_o);
    cudaGetSymbolAddress((void**)&x1,  g_x1);
    cudaGetSymbolAddress((void**)&fc1, g_fc1);

    const int GEMM_SMEM = 2 * GSTAGE * 4;        // 73728
    const int G64_SMEM  = 2 * G64STAGE * 4;      // 55296
    const int ATTN_SMEM = 3 * 64 * 68 * 4;       // 52224
    cudaFuncSetAttribute(gemm_mma<false, false, false>,
                         cudaFuncAttributeMaxDynamicSharedMemorySize, GEMM_SMEM);
    cudaFuncSetAttribute(gemm_mma<true, false, true>,
                         cudaFuncAttributeMaxDynamicSharedMemorySize, GEMM_SMEM);
    cudaFuncSetAttribute(gemm64<true, true, false>,
                         cudaFuncAttributeMaxDynamicSharedMemorySize, G64_SMEM);
    cudaFuncSetAttribute(attn_mma,
                         cudaFuncAttributeMaxDynamicSharedMemorySize, ATTN_SMEM);

    // 1. h = LN1(x)
    ln_kernel<<<NTOK, 256>>>(x, g1, beta1, h);
    // 2. qkv = h @ w_qkv^T
    gemm_mma<false, false, false><<<dim3(QKVD / 128, NTOK / 128), 256, GEMM_SMEM>>>(
        h, w_qkv, nullptr, nullptr, qkv, NTOK, QKVD, CDIM);
    // 3. RoPE(q, k)
    rope_kernel<<<(NTOK * NH * 32 + 255) / 256, 256>>>(qkv, cos_t, sin_t);
    // 4. o = attention(q, k, v)
    attn_mma<<<dim3(NTOK / 64, NH), 128, ATTN_SMEM>>>(qkv, o);
    // 5. x1 = x + o @ w_proj^T + b_proj   (64-row tiles: grid 6x64 = 384)
    gemm64<true, true, false><<<dim3(CDIM / 128, NTOK / 64), 128, G64_SMEM>>>(
        o, w_proj, b_proj, x, x1, NTOK, CDIM, CDIM);
    // 6. h = LN2(x1)
    ln_kernel<<<NTOK, 256>>>(x1, g2, beta2, h);
    // 7. fc1 = gelu(h @ w_fc1^T + b_fc1)
    gemm_mma<true, false, true><<<dim3(FF / 128, NTOK / 128), 256, GEMM_SMEM>>>(
        h, w_fc1, b_fc1, nullptr, fc1, NTOK, FF, CDIM);
    // 8. out = x1 + fc1 @ w_fc2^T + b_fc2  (64-row tiles: grid 6x64 = 384)
    gemm64<true, true, false><<<dim3(CDIM / 128, NTOK / 64), 128, G64_SMEM>>>(
        fc1, w_fc2, b_fc2, x1, out, NTOK, CDIM, FF);
}

// round 7
// speedup vs baseline: 1.2533x; 1.2533x over previous
#include <cuda_runtime.h>
#include <math.h>
#include <stdint.h>

#define NTOK 4096
#define CDIM 768
#define NH   12
#define HD   64
#define FF   3072
#define QKVD 2304

// ---------------- scratch ----------------------------------------------------
__device__ float g_h[NTOK * CDIM];
__device__ float g_qkv[NTOK * QKVD];
__device__ float g_o[NTOK * CDIM];
__device__ float g_x1[NTOK * CDIM];
__device__ float g_fc1[NTOK * FF];

// ---------------- helpers ----------------------------------------------------
__device__ __forceinline__ uint32_t cvt_tf32(float f) {
    uint32_t r;
    asm("cvt.rna.tf32.f32 %0, %1;" : "=r"(r) : "f"(f));
    return r;
}
__device__ __forceinline__ void mma_tf32(float* d, const uint32_t* a, const uint32_t* b) {
    asm volatile(
        "mma.sync.aligned.m16n8k8.row.col.f32.tf32.tf32.f32 "
        "{%0,%1,%2,%3}, {%4,%5,%6,%7}, {%8,%9}, {%0,%1,%2,%3};\n"
        : "+f"(d[0]), "+f"(d[1]), "+f"(d[2]), "+f"(d[3])
        : "r"(a[0]), "r"(a[1]), "r"(a[2]), "r"(a[3]), "r"(b[0]), "r"(b[1]));
}

// 2^x on the FMA pipe (softmax args <= 0; clamp handles sentinels)
__device__ __forceinline__ float fexp2(float x) {
    x = fmaxf(x, -126.0f);
    int e = __float2int_rn(x);
    float f = x - (float)e;
    float p = fmaf(f, 0.00133336f, 0.00961813f);
    p = fmaf(f, p, 0.0555041f);
    p = fmaf(f, p, 0.2402265f);
    p = fmaf(f, p, 0.6931472f);
    p = fmaf(f, p, 1.0f);
    return __int_as_float((e + 127) << 23) * p;
}

// ---------------- LayerNorm --------------------------------------------------
__global__ __launch_bounds__(256) void ln_kernel(
    const float* __restrict__ x, const float* __restrict__ g,
    const float* __restrict__ b, float* __restrict__ out)
{
    const int row = blockIdx.x;
    const int tid = threadIdx.x;
    const float* xr = x + row * CDIM;
    float v[3];
    float s = 0.f;
#pragma unroll
    for (int i = 0; i < 3; i++) { v[i] = xr[tid + 256 * i]; s += v[i]; }

    __shared__ float sh[8];
#pragma unroll
    for (int o = 16; o > 0; o >>= 1) s += __shfl_xor_sync(0xffffffffu, s, o);
    if ((tid & 31) == 0) sh[tid >> 5] = s;
    __syncthreads();
    if (tid < 8) {
        s = sh[tid];
#pragma unroll
        for (int o = 4; o > 0; o >>= 1) s += __shfl_xor_sync(0xffu, s, o);
        if (tid == 0) sh[0] = s;
    }
    __syncthreads();
    const float mu = sh[0] * (1.0f / CDIM);
    __syncthreads();

    float s2 = 0.f;
#pragma unroll
    for (int i = 0; i < 3; i++) { float d = v[i] - mu; s2 += d * d; }
#pragma unroll
    for (int o = 16; o > 0; o >>= 1) s2 += __shfl_xor_sync(0xffffffffu, s2, o);
    if ((tid & 31) == 0) sh[tid >> 5] = s2;
    __syncthreads();
    if (tid < 8) {
        s2 = sh[tid];
#pragma unroll
        for (int o = 4; o > 0; o >>= 1) s2 += __shfl_xor_sync(0xffu, s2, o);
        if (tid == 0) sh[0] = s2;
    }
    __syncthreads();
    const float rstd = rsqrtf(sh[0] * (1.0f / CDIM) + 1e-5f);

    float* orow = out + row * CDIM;
#pragma unroll
    for (int i = 0; i < 3; i++) {
        int c = tid + 256 * i;
        orow[c] = (v[i] - mu) * rstd * g[c] + b[c];
    }
}

// ---------------- tf32 mma GEMM-NT: C[M,N] = A[M,K]*B[N,K]^T (+epilogue) -----
// CTA 128x128, BK=32, 8 warps (4 M x 2 N), warp tile 32x64. (R5 proven)
#define GSA 36
#define GSTAGE (2 * 128 * GSA)

template <bool HAS_BIAS, bool HAS_RES, bool DO_GELU>
__global__ __launch_bounds__(256) void gemm_mma(
    const float* __restrict__ A, const float* __restrict__ B,
    const float* __restrict__ bias, const float* __restrict__ res,
    float* __restrict__ C, int M, int Nc, int K)
{
    extern __shared__ float sm[];
    const int tid = threadIdx.x;
    const int lane = tid & 31;
    const int wid = tid >> 5;
    const int wm = (wid & 3) * 32;
    const int wn = (wid >> 2) * 64;
    const int m0 = blockIdx.y * 128;
    const int n0 = blockIdx.x * 128;
    const int r = lane >> 2;
    const int q = lane & 3;

    const int lrow = tid >> 1;
    const int lcol = (tid & 1) * 16;
    const float* Ag = A + (long)(m0 + lrow) * K + lcol;
    const float* Bg = B + (long)(n0 + lrow) * K + lcol;
    const int ktiles = K >> 5;

    float acc[2][8][4];
#pragma unroll
    for (int mt = 0; mt < 2; mt++)
#pragma unroll
        for (int nt = 0; nt < 8; nt++)
#pragma unroll
            for (int j = 0; j < 4; j++) acc[mt][nt][j] = 0.f;

    float4 ra[4], rb[4];
#pragma unroll
    for (int v = 0; v < 4; v++) {
        ra[v] = *(const float4*)(Ag + v * 4);
        rb[v] = *(const float4*)(Bg + v * 4);
    }
    {
        uint32_t* Au = (uint32_t*)sm;
        uint32_t* Bu = Au + 128 * GSA;
#pragma unroll
        for (int v = 0; v < 4; v++) {
            int off = lrow * GSA + lcol + v * 4;
            uint4 at = {cvt_tf32(ra[v].x), cvt_tf32(ra[v].y), cvt_tf32(ra[v].z), cvt_tf32(ra[v].w)};
            uint4 bt = {cvt_tf32(rb[v].x), cvt_tf32(rb[v].y), cvt_tf32(rb[v].z), cvt_tf32(rb[v].w)};
            *(uint4*)(Au + off) = at;
            *(uint4*)(Bu + off) = bt;
        }
    }
    if (ktiles > 1) {
#pragma unroll
        for (int v = 0; v < 4; v++) {
            ra[v] = *(const float4*)(Ag + 32 + v * 4);
            rb[v] = *(const float4*)(Bg + 32 + v * 4);
        }
    }
    __syncthreads();

    for (int kt = 0; kt < ktiles; kt++) {
        const int b = kt & 1;
        if (kt + 1 < ktiles) {
            uint32_t* Au = (uint32_t*)(sm + (b ^ 1) * GSTAGE);
            uint32_t* Bu = Au + 128 * GSA;
#pragma unroll
            for (int v = 0; v < 4; v++) {
                int off = lrow * GSA + lcol + v * 4;
                uint4 at = {cvt_tf32(ra[v].x), cvt_tf32(ra[v].y), cvt_tf32(ra[v].z), cvt_tf32(ra[v].w)};
                uint4 bt = {cvt_tf32(rb[v].x), cvt_tf32(rb[v].y), cvt_tf32(rb[v].z), cvt_tf32(rb[v].w)};
                *(uint4*)(Au + off) = at;
                *(uint4*)(Bu + off) = bt;
            }
            if (kt + 2 < ktiles) {
#pragma unroll
                for (int v = 0; v < 4; v++) {
                    ra[v] = *(const float4*)(Ag + (kt + 2) * 32 + v * 4);
                    rb[v] = *(const float4*)(Bg + (kt + 2) * 32 + v * 4);
                }
            }
        }
        {
            const uint32_t* Au = (const uint32_t*)(sm + b * GSTAGE);
            const uint32_t* Bu = Au + 128 * GSA;
#pragma unroll
            for (int kc = 0; kc < 4; kc++) {
                uint32_t af[2][4];
#pragma unroll
                for (int mt = 0; mt < 2; mt++) {
                    const uint32_t* base = Au + (wm + mt * 16 + r) * GSA + kc * 8 + q;
                    af[mt][0] = base[0];
                    af[mt][1] = base[8 * GSA];
                    af[mt][2] = base[4];
                    af[mt][3] = base[8 * GSA + 4];
                }
#pragma unroll
                for (int nt = 0; nt < 8; nt++) {
                    uint32_t bf[2];
                    const uint32_t* base = Bu + (wn + nt * 8 + r) * GSA + kc * 8 + q;
                    bf[0] = base[0];
                    bf[1] = base[4];
#pragma unroll
                    for (int mt = 0; mt < 2; mt++)
                        mma_tf32(acc[mt][nt], af[mt], bf);
                }
            }
        }
        __syncthreads();
    }

#pragma unroll
    for (int mt = 0; mt < 2; mt++) {
#pragma unroll
        for (int rr = 0; rr < 2; rr++) {
            const int m = m0 + wm + mt * 16 + r + rr * 8;
            float* crow = C + (long)m * Nc;
            const float* rrow = HAS_RES ? (res + (long)m * Nc) : nullptr;
#pragma unroll
            for (int nt = 0; nt < 8; nt++) {
                const int n = n0 + wn + nt * 8 + 2 * q;
                float v0 = acc[mt][nt][rr * 2 + 0];
                float v1 = acc[mt][nt][rr * 2 + 1];
                if (HAS_BIAS) { v0 += bias[n]; v1 += bias[n + 1]; }
                if (DO_GELU) {
                    v0 = 0.5f * v0 * (1.0f + erff(v0 * 0.70710678118654752f));
                    v1 = 0.5f * v1 * (1.0f + erff(v1 * 0.70710678118654752f));
                }
                if (HAS_RES) { v0 += rrow[n]; v1 += rrow[n + 1]; }
                float2 w = {v0, v1};
                *(float2*)(crow + n) = w;
            }
        }
    }
}

// ---------------- RoPE -------------------------------------------------------
__global__ __launch_bounds__(256) void rope_kernel(
    float* __restrict__ qkv, const float* __restrict__ cos_t,
    const float* __restrict__ sin_t)
{
    int idx = blockIdx.x * blockDim.x + threadIdx.x;
    if (idx >= NTOK * NH * (HD / 2)) return;
    const int i = idx & 31;
    const int h = (idx >> 5) % NH;
    const int n = idx / (NH * (HD / 2));
    const float c = cos_t[n * 32 + i];
    const float s = sin_t[n * 32 + i];
#pragma unroll
    for (int sel = 0; sel < 2; sel++) {
        float* p = qkv + (long)n * QKVD + sel * CDIM + h * HD + 2 * i;
        float t0 = p[0], t1 = p[1];
        p[0] = t0 * c - t1 * s;
        p[1] = t0 * s + t1 * c;
    }
}

// ---------------- flash attention: 128 q-rows, 4 warps, warp M=32 ------------
// Q fragments cached in registers (qf[8][2][4]); smem Q buffer reused for P.
// B-fragments (K,V) loaded once per warp, shared across both m-subtiles.
// smem: Ks[key][d] 64x68, Vs[d][key] 64x68 (transposed), QP[128][68].
__global__ __launch_bounds__(128, 2) void attn_mma(
    const float* __restrict__ qkv, float* __restrict__ out)
{
    extern __shared__ float sm[];
    float* Ks = sm;                 // [key][d]
    float* Vs = sm + 64 * 68;       // [d][key] transposed
    float* QP = sm + 2 * 64 * 68;   // [128][68]: Q staging, then per-warp P

    const int tid = threadIdx.x;
    const int lane = tid & 31;
    const int wid = tid >> 5;       // 0..3
    const int h = blockIdx.y;
    const int q0 = blockIdx.x * 128;
    const int r = lane >> 2;
    const int q = lane & 3;
    const float QSCALE = 0.125f * 1.4426950408889634f;   // scale * log2e

    // stage Q (scaled, tf32): one full row per thread
    {
        const float* qp = qkv + (long)(q0 + tid) * QKVD + h * HD;
        uint32_t* dst = (uint32_t*)(QP + tid * 68);
#pragma unroll
        for (int v = 0; v < 16; v++) {
            float4 t = *(const float4*)(qp + v * 4);
            dst[v * 4 + 0] = cvt_tf32(t.x * QSCALE);
            dst[v * 4 + 1] = cvt_tf32(t.y * QSCALE);
            dst[v * 4 + 2] = cvt_tf32(t.z * QSCALE);
            dst[v * 4 + 3] = cvt_tf32(t.w * QSCALE);
        }
    }
    __syncthreads();

    // extract Q a-fragments for warp tile 32 rows x 64 d (8 k-steps, 2 m-subtiles)
    uint32_t qf[8][2][4];
    {
        const uint32_t* Qu = (const uint32_t*)(QP + wid * 32 * 68);
#pragma unroll
        for (int kc = 0; kc < 8; kc++)
#pragma unroll
            for (int mt = 0; mt < 2; mt++) {
                const uint32_t* b = Qu + (mt * 16 + r) * 68 + kc * 8 + q;
                qf[kc][mt][0] = b[0];
                qf[kc][mt][1] = b[8 * 68];
                qf[kc][mt][2] = b[4];
                qf[kc][mt][3] = b[8 * 68 + 4];
            }
    }
    __syncthreads();   // QP now reusable as P

    float mv[2][2], lv[2][2];
    float of[2][8][4];
#pragma unroll
    for (int mt = 0; mt < 2; mt++) {
        mv[mt][0] = -1e30f; mv[mt][1] = -1e30f;
        lv[mt][0] = 0.f; lv[mt][1] = 0.f;
#pragma unroll
        for (int nt = 0; nt < 8; nt++)
#pragma unroll
            for (int j = 0; j < 4; j++) of[mt][nt][j] = 0.f;
    }

    uint32_t* Pu = (uint32_t*)(QP + wid * 32 * 68);

    for (int kt = 0; kt < NTOK / 64; kt++) {
        // stage K [key][d], V [d][key] transposed: kr = tid&63, 32 cols each
        {
            const int kr = tid & 63;
            const int c0 = (tid >> 6) * 32;
            const float* kp = qkv + (long)(kt * 64 + kr) * QKVD + CDIM + h * HD + c0;
            const float* vp = kp + CDIM;
            uint32_t* kd = (uint32_t*)(Ks + kr * 68 + c0);
            uint32_t* vd = (uint32_t*)Vs;
#pragma unroll
            for (int v = 0; v < 8; v++) {
                float4 kk = *(const float4*)(kp + v * 4);
                uint4 kt4 = {cvt_tf32(kk.x), cvt_tf32(kk.y), cvt_tf32(kk.z), cvt_tf32(kk.w)};
                *(uint4*)(kd + v * 4) = kt4;
                float4 vvv = *(const float4*)(vp + v * 4);
                vd[(c0 + v * 4 + 0) * 68 + kr] = cvt_tf32(vvv.x);
                vd[(c0 + v * 4 + 1) * 68 + kr] = cvt_tf32(vvv.y);
                vd[(c0 + v * 4 + 2) * 68 + kr] = cvt_tf32(vvv.z);
                vd[(c0 + v * 4 + 3) * 68 + kr] = cvt_tf32(vvv.w);
            }
        }
        __syncthreads();

        // S = Q K^T : 32x64 warp tile (log2 domain); B-frags shared across mt
        float sf[2][8][4];
#pragma unroll
        for (int mt = 0; mt < 2; mt++)
#pragma unroll
            for (int nt = 0; nt < 8; nt++)
#pragma unroll
                for (int j = 0; j < 4; j++) sf[mt][nt][j] = 0.f;
        {
            const uint32_t* Ku = (const uint32_t*)Ks;
#pragma unroll
            for (int kc = 0; kc < 8; kc++) {
#pragma unroll
                for (int nt = 0; nt < 8; nt++) {
                    uint32_t bf[2];
                    const uint32_t* bb = Ku + (nt * 8 + r) * 68 + kc * 8 + q;
                    bf[0] = bb[0];
                    bf[1] = bb[4];
                    mma_tf32(sf[0][nt], qf[kc][0], bf);
                    mma_tf32(sf[1][nt], qf[kc][1], bf);
                }
            }
        }

        // online softmax per m-subtile; write P to per-warp smem
#pragma unroll
        for (int mt = 0; mt < 2; mt++) {
            float rm0 = -1e30f, rm1 = -1e30f;
#pragma unroll
            for (int nt = 0; nt < 8; nt++) {
                rm0 = fmaxf(rm0, fmaxf(sf[mt][nt][0], sf[mt][nt][1]));
                rm1 = fmaxf(rm1, fmaxf(sf[mt][nt][2], sf[mt][nt][3]));
            }
            rm0 = fmaxf(rm0, __shfl_xor_sync(0xffffffffu, rm0, 1));
            rm0 = fmaxf(rm0, __shfl_xor_sync(0xffffffffu, rm0, 2));
            rm1 = fmaxf(rm1, __shfl_xor_sync(0xffffffffu, rm1, 1));
            rm1 = fmaxf(rm1, __shfl_xor_sync(0xffffffffu, rm1, 2));
            const float mn0 = fmaxf(mv[mt][0], rm0);
            const float mn1 = fmaxf(mv[mt][1], rm1);
            const float corr0 = fexp2(mv[mt][0] - mn0);
            const float corr1 = fexp2(mv[mt][1] - mn1);
            float rs0 = 0.f, rs1 = 0.f;
#pragma unroll
            for (int nt = 0; nt < 8; nt++) {
                float p0 = fexp2(sf[mt][nt][0] - mn0);
                float p1 = fexp2(sf[mt][nt][1] - mn0);
                float p2 = fexp2(sf[mt][nt][2] - mn1);
                float p3 = fexp2(sf[mt][nt][3] - mn1);
                rs0 += p0 + p1;
                rs1 += p2 + p3;
                uint2 w0 = {cvt_tf32(p0), cvt_tf32(p1)};
                uint2 w1 = {cvt_tf32(p2), cvt_tf32(p3)};
                *(uint2*)(Pu + (mt * 16 + r) * 68 + nt * 8 + 2 * q) = w0;
                *(uint2*)(Pu + (mt * 16 + r + 8) * 68 + nt * 8 + 2 * q) = w1;
            }
            rs0 += __shfl_xor_sync(0xffffffffu, rs0, 1);
            rs0 += __shfl_xor_sync(0xffffffffu, rs0, 2);
            rs1 += __shfl_xor_sync(0xffffffffu, rs1, 1);
            rs1 += __shfl_xor_sync(0xffffffffu, rs1, 2);
            lv[mt][0] = lv[mt][0] * corr0 + rs0;
            lv[mt][1] = lv[mt][1] * corr1 + rs1;
            mv[mt][0] = mn0;
            mv[mt][1] = mn1;
#pragma unroll
            for (int nt = 0; nt < 8; nt++) {
                of[mt][nt][0] *= corr0; of[mt][nt][1] *= corr0;
                of[mt][nt][2] *= corr1; of[mt][nt][3] *= corr1;
            }
        }
        __syncwarp();

        // O += P V (V transposed: conflict-free B frags, shared across mt)
        {
            const uint32_t* Vu = (const uint32_t*)Vs;
#pragma unroll
            for (int kc = 0; kc < 8; kc++) {
                uint32_t ap[2][4];
#pragma unroll
                for (int mt = 0; mt < 2; mt++) {
                    const uint32_t* ab = Pu + (mt * 16 + r) * 68 + kc * 8 + q;
                    ap[mt][0] = ab[0];
                    ap[mt][1] = ab[8 * 68];
                    ap[mt][2] = ab[4];
                    ap[mt][3] = ab[8 * 68 + 4];
                }
#pragma unroll
                for (int nt = 0; nt < 8; nt++) {
                    uint32_t bf[2];
                    const uint32_t* bb = Vu + (nt * 8 + r) * 68 + kc * 8 + q;
                    bf[0] = bb[0];
                    bf[1] = bb[4];
                    mma_tf32(of[0][nt], ap[0], bf);
                    mma_tf32(of[1][nt], ap[1], bf);
                }
            }
        }
        __syncthreads();
    }

    // normalize + store
#pragma unroll
    for (int mt = 0; mt < 2; mt++) {
        const float inv0 = 1.0f / lv[mt][0];
        const float inv1 = 1.0f / lv[mt][1];
        const int row0 = q0 + wid * 32 + mt * 16 + r;
#pragma unroll
        for (int nt = 0; nt < 8; nt++) {
            const int col = h * HD + nt * 8 + 2 * q;
            float2 w0 = {of[mt][nt][0] * inv0, of[mt][nt][1] * inv0};
            float2 w1 = {of[mt][nt][2] * inv1, of[mt][nt][3] * inv1};
            *(float2*)(out + (long)row0 * CDIM + col) = w0;
            *(float2*)(out + (long)(row0 + 8) * CDIM + col) = w1;
        }
    }
}

// ---------------- launch -----------------------------------------------------
extern "C" void kernel_launch(void* const* d_in, const int* in_sizes, int n_in,
                              void* d_out, int out_size)
{
    const float* x      = (const float*)d_in[0];
    const float* cos_t  = (const float*)d_in[1];
    const float* sin_t  = (const float*)d_in[2];
    const float* w_qkv  = (const float*)d_in[3];
    const float* w_proj = (const float*)d_in[4];
    const float* b_proj = (const float*)d_in[5];
    const float* g1     = (const float*)d_in[6];
    const float* beta1  = (const float*)d_in[7];
    const float* g2     = (const float*)d_in[8];
    const float* beta2  = (const float*)d_in[9];
    const float* w_fc1  = (const float*)d_in[10];
    const float* b_fc1  = (const float*)d_in[11];
    const float* w_fc2  = (const float*)d_in[12];
    const float* b_fc2  = (const float*)d_in[13];
    float* out = (float*)d_out;

    float *h, *qkv, *o, *x1, *fc1;
    cudaGetSymbolAddress((void**)&h,   g_h);
    cudaGetSymbolAddress((void**)&qkv, g_qkv);
    cudaGetSymbolAddress((void**)&o,   g_o);
    cudaGetSymbolAddress((void**)&x1,  g_x1);
    cudaGetSymbolAddress((void**)&fc1, g_fc1);

    const int GEMM_SMEM = 2 * GSTAGE * 4;           // 73728
    const int ATTN_SMEM = (2 * 64 + 128) * 68 * 4;  // 69632
    cudaFuncSetAttribute(gemm_mma<false, false, false>,
                         cudaFuncAttributeMaxDynamicSharedMemorySize, GEMM_SMEM);
    cudaFuncSetAttribute(gemm_mma<true, true, false>,
                         cudaFuncAttributeMaxDynamicSharedMemorySize, GEMM_SMEM);
    cudaFuncSetAttribute(gemm_mma<true, false, true>,
                         cudaFuncAttributeMaxDynamicSharedMemorySize, GEMM_SMEM);
    cudaFuncSetAttribute(attn_mma,
                         cudaFuncAttributeMaxDynamicSharedMemorySize, ATTN_SMEM);

    // 1. h = LN1(x)
    ln_kernel<<<NTOK, 256>>>(x, g1, beta1, h);
    // 2. qkv = h @ w_qkv^T
    gemm_mma<false, false, false><<<dim3(QKVD / 128, NTOK / 128), 256, GEMM_SMEM>>>(
        h, w_qkv, nullptr, nullptr, qkv, NTOK, QKVD, CDIM);
    // 3. RoPE(q, k)
    rope_kernel<<<(NTOK * NH * 32 + 255) / 256, 256>>>(qkv, cos_t, sin_t);
    // 4. o = attention(q, k, v)
    attn_mma<<<dim3(NTOK / 128, NH), 128, ATTN_SMEM>>>(qkv, o);
    // 5. x1 = x + o @ w_proj^T + b_proj
    gemm_mma<true, true, false><<<dim3(CDIM / 128, NTOK / 128), 256, GEMM_SMEM>>>(
        o, w_proj, b_proj, x, x1, NTOK, CDIM, CDIM);
    // 6. h = LN2(x1)
    ln_kernel<<<NTOK, 256>>>(x1, g2, beta2, h);
    // 7. fc1 = gelu(h @ w_fc1^T + b_fc1)
    gemm_mma<true, false, true><<<dim3(FF / 128, NTOK / 128), 256, GEMM_SMEM>>>(
        h, w_fc1, b_fc1, nullptr, fc1, NTOK, FF, CDIM);
    // 8. out = x1 + fc1 @ w_fc2^T + b_fc2
    gemm_mma<true, true, false><<<dim3(CDIM / 128, NTOK / 128), 256, GEMM_SMEM>>>(
        fc1, w_fc2, b_fc2, x1, out, NTOK, CDIM, FF);
}

// round 8
// speedup vs baseline: 1.3049x; 1.0411x over previous
#include <cuda_runtime.h>
#include <math.h>
#include <stdint.h>

#define NTOK 4096
#define CDIM 768
#define NH   12
#define HD   64
#define FF   3072
#define QKVD 2304

// ---------------- scratch ----------------------------------------------------
__device__ float g_h[NTOK * CDIM];
__device__ float g_qkv[NTOK * QKVD];
__device__ float g_o[NTOK * CDIM];
__device__ float g_x1[NTOK * CDIM];
__device__ float g_fc1[NTOK * FF];
// tf32-pre-rounded weights
__device__ float g_wq[QKVD * CDIM];
__device__ float g_wp[CDIM * CDIM];
__device__ float g_w1[FF * CDIM];
__device__ float g_w2[CDIM * FF];

// ---------------- helpers ----------------------------------------------------
__device__ __forceinline__ uint32_t smem_u32(const void* p) {
    uint32_t a;
    asm("{ .reg .u64 t; cvta.to.shared.u64 t, %1; cvt.u32.u64 %0, t; }" : "=r"(a) : "l"(p));
    return a;
}
__device__ __forceinline__ uint32_t cvt_tf32(float f) {
    uint32_t r;
    asm("cvt.rna.tf32.f32 %0, %1;" : "=r"(r) : "f"(f));
    return r;
}
__device__ __forceinline__ float round_tf32f(float f) {
    return __uint_as_float(cvt_tf32(f));
}
__device__ __forceinline__ void mma_tf32(float* d, const uint32_t* a, const uint32_t* b) {
    asm volatile(
        "mma.sync.aligned.m16n8k8.row.col.f32.tf32.tf32.f32 "
        "{%0,%1,%2,%3}, {%4,%5,%6,%7}, {%8,%9}, {%0,%1,%2,%3};\n"
        : "+f"(d[0]), "+f"(d[1]), "+f"(d[2]), "+f"(d[3])
        : "r"(a[0]), "r"(a[1]), "r"(a[2]), "r"(a[3]), "r"(b[0]), "r"(b[1]));
}
__device__ __forceinline__ void cp16(void* smem_dst, const void* gmem_src) {
    uint32_t s = smem_u32(smem_dst);
    asm volatile("cp.async.cg.shared.global [%0], [%1], 16;" :: "r"(s), "l"(gmem_src));
}
#define CP_COMMIT() asm volatile("cp.async.commit_group;" ::: "memory")
#define CP_WAIT(n)  asm volatile("cp.async.wait_group %0;" :: "n"(n) : "memory")

// 2^x on the FMA pipe
__device__ __forceinline__ float fexp2(float x) {
    x = fmaxf(x, -126.0f);
    int e = __float2int_rn(x);
    float f = x - (float)e;
    float p = fmaf(f, 0.00133336f, 0.00961813f);
    p = fmaf(f, p, 0.0555041f);
    p = fmaf(f, p, 0.2402265f);
    p = fmaf(f, p, 0.6931472f);
    p = fmaf(f, p, 1.0f);
    return __int_as_float((e + 127) << 23) * p;
}

// ---------------- weight rounding prep ---------------------------------------
__global__ __launch_bounds__(256) void round_kernel(const float* __restrict__ src,
                                                    float* __restrict__ dst) {
    int i = (blockIdx.x * 256 + threadIdx.x) * 4;
    float4 v = *(const float4*)(src + i);
    v.x = round_tf32f(v.x); v.y = round_tf32f(v.y);
    v.z = round_tf32f(v.z); v.w = round_tf32f(v.w);
    *(float4*)(dst + i) = v;
}

// ---------------- LayerNorm (tf32-rounded output) ----------------------------
__global__ __launch_bounds__(256) void ln_kernel(
    const float* __restrict__ x, const float* __restrict__ g,
    const float* __restrict__ b, float* __restrict__ out)
{
    const int row = blockIdx.x;
    const int tid = threadIdx.x;
    const float* xr = x + row * CDIM;
    float v[3];
    float s = 0.f;
#pragma unroll
    for (int i = 0; i < 3; i++) { v[i] = xr[tid + 256 * i]; s += v[i]; }

    __shared__ float sh[8];
#pragma unroll
    for (int o = 16; o > 0; o >>= 1) s += __shfl_xor_sync(0xffffffffu, s, o);
    if ((tid & 31) == 0) sh[tid >> 5] = s;
    __syncthreads();
    if (tid < 8) {
        s = sh[tid];
#pragma unroll
        for (int o = 4; o > 0; o >>= 1) s += __shfl_xor_sync(0xffu, s, o);
        if (tid == 0) sh[0] = s;
    }
    __syncthreads();
    const float mu = sh[0] * (1.0f / CDIM);
    __syncthreads();

    float s2 = 0.f;
#pragma unroll
    for (int i = 0; i < 3; i++) { float d = v[i] - mu; s2 += d * d; }
#pragma unroll
    for (int o = 16; o > 0; o >>= 1) s2 += __shfl_xor_sync(0xffffffffu, s2, o);
    if ((tid & 31) == 0) sh[tid >> 5] = s2;
    __syncthreads();
    if (tid < 8) {
        s2 = sh[tid];
#pragma unroll
        for (int o = 4; o > 0; o >>= 1) s2 += __shfl_xor_sync(0xffu, s2, o);
        if (tid == 0) sh[0] = s2;
    }
    __syncthreads();
    const float rstd = rsqrtf(sh[0] * (1.0f / CDIM) + 1e-5f);

    float* orow = out + row * CDIM;
#pragma unroll
    for (int i = 0; i < 3; i++) {
        int c = tid + 256 * i;
        orow[c] = round_tf32f((v[i] - mu) * rstd * g[c] + b[c]);
    }
}

// ---------------- tf32 GEMM-NT, cp.async staged ------------------------------
// CTA 128x128, BK=32, 8 warps (4M x 2N), warp tile 32x64, 2-stage cp.async.
// All inputs MUST be tf32-pre-rounded fp32.
#define GSA 36
#define GSTAGE (2 * 128 * GSA)   // floats per stage (A+B)

template <bool HAS_BIAS, bool HAS_RES, bool DO_GELU, bool ROUND_OUT>
__global__ __launch_bounds__(256) void gemm_cp(
    const float* __restrict__ A, const float* __restrict__ B,
    const float* __restrict__ bias, const float* __restrict__ res,
    float* __restrict__ C, int M, int Nc, int K)
{
    extern __shared__ float sm[];
    const int tid = threadIdx.x;
    const int lane = tid & 31;
    const int wid = tid >> 5;
    const int wm = (wid & 3) * 32;
    const int wn = (wid >> 2) * 64;
    const int m0 = blockIdx.y * 128;
    const int n0 = blockIdx.x * 128;
    const int r = lane >> 2;
    const int q = lane & 3;

    const int row = tid >> 1;           // 0..127
    const int seg = (tid & 1) * 16;     // 0 or 16
    const float* Ag = A + (long)(m0 + row) * K + seg;
    const float* Bg = B + (long)(n0 + row) * K + seg;
    const int ktiles = K >> 5;

    float acc[2][8][4];
#pragma unroll
    for (int mt = 0; mt < 2; mt++)
#pragma unroll
        for (int nt = 0; nt < 8; nt++)
#pragma unroll
            for (int j = 0; j < 4; j++) acc[mt][nt][j] = 0.f;

    auto issue = [&](int kt, int s) {
        float* As = sm + s * GSTAGE;
        float* Bs = As + 128 * GSA;
        const int off = row * GSA + seg;
#pragma unroll
        for (int v = 0; v < 4; v++) cp16(As + off + v * 4, Ag + kt * 32 + v * 4);
#pragma unroll
        for (int v = 0; v < 4; v++) cp16(Bs + off + v * 4, Bg + kt * 32 + v * 4);
    };

    issue(0, 0);
    CP_COMMIT();

    for (int kt = 0; kt < ktiles; kt++) {
        if (kt + 1 < ktiles) {
            issue(kt + 1, (kt + 1) & 1);
            CP_COMMIT();
            CP_WAIT(1);
        } else {
            CP_WAIT(0);
        }
        __syncthreads();

        const uint32_t* Au = (const uint32_t*)(sm + (kt & 1) * GSTAGE);
        const uint32_t* Bu = Au + 128 * GSA;
#pragma unroll
        for (int kc = 0; kc < 4; kc++) {
            uint32_t af[2][4];
#pragma unroll
            for (int mt = 0; mt < 2; mt++) {
                const uint32_t* base = Au + (wm + mt * 16 + r) * GSA + kc * 8 + q;
                af[mt][0] = base[0];
                af[mt][1] = base[8 * GSA];
                af[mt][2] = base[4];
                af[mt][3] = base[8 * GSA + 4];
            }
#pragma unroll
            for (int nt = 0; nt < 8; nt++) {
                uint32_t bf[2];
                const uint32_t* base = Bu + (wn + nt * 8 + r) * GSA + kc * 8 + q;
                bf[0] = base[0];
                bf[1] = base[4];
#pragma unroll
                for (int mt = 0; mt < 2; mt++)
                    mma_tf32(acc[mt][nt], af[mt], bf);
            }
        }
        __syncthreads();
    }

#pragma unroll
    for (int mt = 0; mt < 2; mt++) {
#pragma unroll
        for (int rr = 0; rr < 2; rr++) {
            const int m = m0 + wm + mt * 16 + r + rr * 8;
            float* crow = C + (long)m * Nc;
            const float* rrow = HAS_RES ? (res + (long)m * Nc) : nullptr;
#pragma unroll
            for (int nt = 0; nt < 8; nt++) {
                const int n = n0 + wn + nt * 8 + 2 * q;
                float v0 = acc[mt][nt][rr * 2 + 0];
                float v1 = acc[mt][nt][rr * 2 + 1];
                if (HAS_BIAS) { v0 += bias[n]; v1 += bias[n + 1]; }
                if (DO_GELU) {
                    v0 = 0.5f * v0 * (1.0f + erff(v0 * 0.70710678118654752f));
                    v1 = 0.5f * v1 * (1.0f + erff(v1 * 0.70710678118654752f));
                }
                if (HAS_RES) { v0 += rrow[n]; v1 += rrow[n + 1]; }
                if (ROUND_OUT) { v0 = round_tf32f(v0); v1 = round_tf32f(v1); }
                float2 w = {v0, v1};
                *(float2*)(crow + n) = w;
            }
        }
    }
}

// ---------------- RoPE (rounds q,k; folds softmax scale into q) --------------
__global__ __launch_bounds__(256) void rope_kernel(
    float* __restrict__ qkv, const float* __restrict__ cos_t,
    const float* __restrict__ sin_t)
{
    const float QSCALE = 0.125f * 1.4426950408889634f;   // 1/sqrt(64) * log2e
    int idx = blockIdx.x * blockDim.x + threadIdx.x;
    if (idx >= NTOK * NH * (HD / 2)) return;
    const int i = idx & 31;
    const int h = (idx >> 5) % NH;
    const int n = idx / (NH * (HD / 2));
    const float c = cos_t[n * 32 + i];
    const float s = sin_t[n * 32 + i];
    {   // q: rotate, scale, round
        float* p = qkv + (long)n * QKVD + h * HD + 2 * i;
        float t0 = p[0], t1 = p[1];
        p[0] = round_tf32f((t0 * c - t1 * s) * QSCALE);
        p[1] = round_tf32f((t0 * s + t1 * c) * QSCALE);
    }
    {   // k: rotate, round
        float* p = qkv + (long)n * QKVD + CDIM + h * HD + 2 * i;
        float t0 = p[0], t1 = p[1];
        p[0] = round_tf32f(t0 * c - t1 * s);
        p[1] = round_tf32f(t0 * s + t1 * c);
    }
}

// ---------------- flash attention: cp.async K, pre-rounded operands ----------
// CTA: 128 q-rows x one head; 8 warps, warp = 16 q-rows. Key tiles of 64.
// smem: Ks0,Ks1 [key][d] 64x68 (double-buffered, cp.async),
//       Vs [d][key] 64x68 (transposed), QP [128][68] (Q staging, then P).
__global__ __launch_bounds__(256, 2) void attn_mma(
    const float* __restrict__ qkv, float* __restrict__ out)
{
    extern __shared__ float sm[];
    float* Ks0 = sm;
    float* Ks1 = sm + 64 * 68;
    float* Vs  = sm + 2 * 64 * 68;
    float* QP  = sm + 3 * 64 * 68;

    const int tid = threadIdx.x;
    const int lane = tid & 31;
    const int wid = tid >> 5;
    const int h = blockIdx.y;
    const int q0 = blockIdx.x * 128;
    const int r = lane >> 2;
    const int q = lane & 3;

    const int kr = tid & 63;           // key row handled by this thread
    const int c0 = (tid >> 6) * 16;    // 16-float segment within 64

    // stage Q via cp.async (pre-scaled+rounded by rope)
    {
        const int row = tid >> 1;
        const int cq = (tid & 1) * 32;
        const float* qp = qkv + (long)(q0 + row) * QKVD + h * HD + cq;
        float* dst = QP + row * 68 + cq;
#pragma unroll
        for (int v = 0; v < 8; v++) cp16(dst + v * 4, qp + v * 4);
    }
    // stage K tile 0 via cp.async
    {
        const float* kp = qkv + (long)kr * QKVD + CDIM + h * HD + c0;
        float* dst = Ks0 + kr * 68 + c0;
#pragma unroll
        for (int v = 0; v < 4; v++) cp16(dst + v * 4, kp + v * 4);
    }
    CP_COMMIT();
    CP_WAIT(0);
    __syncthreads();

    // extract Q a-fragments (16 rows x 64 d per warp)
    uint32_t qf[8][4];
    {
        const uint32_t* Qu = (const uint32_t*)(QP + wid * 16 * 68);
#pragma unroll
        for (int kc = 0; kc < 8; kc++) {
            const uint32_t* b = Qu + r * 68 + kc * 8 + q;
            qf[kc][0] = b[0];
            qf[kc][1] = b[8 * 68];
            qf[kc][2] = b[4];
            qf[kc][3] = b[8 * 68 + 4];
        }
    }
    __syncthreads();   // QP now reusable as P

    float m0v = -1e30f, m1v = -1e30f, l0 = 0.f, l1 = 0.f;
    float of[8][4];
#pragma unroll
    for (int nt = 0; nt < 8; nt++)
#pragma unroll
        for (int j = 0; j < 4; j++) of[nt][j] = 0.f;

    uint32_t* Pu = (uint32_t*)(QP + wid * 16 * 68);
    const int ntiles = NTOK / 64;

    for (int kt = 0; kt < ntiles; kt++) {
        // stage V(kt) transposed (no cvt — pre-rounded)
        {
            const float* vp = qkv + (long)(kt * 64 + kr) * QKVD + 2 * CDIM + h * HD + c0;
#pragma unroll
            for (int v = 0; v < 4; v++) {
                float4 t = *(const float4*)(vp + v * 4);
                Vs[(c0 + v * 4 + 0) * 68 + kr] = t.x;
                Vs[(c0 + v * 4 + 1) * 68 + kr] = t.y;
                Vs[(c0 + v * 4 + 2) * 68 + kr] = t.z;
                Vs[(c0 + v * 4 + 3) * 68 + kr] = t.w;
            }
        }
        // prefetch K(kt+1)
        if (kt + 1 < ntiles) {
            const float* kp = qkv + (long)((kt + 1) * 64 + kr) * QKVD + CDIM + h * HD + c0;
            float* dst = ((kt + 1) & 1 ? Ks1 : Ks0) + kr * 68 + c0;
#pragma unroll
            for (int v = 0; v < 4; v++) cp16(dst + v * 4, kp + v * 4);
            CP_COMMIT();
            CP_WAIT(1);
        } else {
            CP_WAIT(0);
        }
        __syncthreads();   // K(kt) + V(kt) visible

        // S = Q K^T : warp 16x64 tile (log2 domain)
        float sf[8][4];
#pragma unroll
        for (int nt = 0; nt < 8; nt++)
#pragma unroll
            for (int j = 0; j < 4; j++) sf[nt][j] = 0.f;
        {
            const uint32_t* Ku = (const uint32_t*)(kt & 1 ? Ks1 : Ks0);
#pragma unroll
            for (int kc = 0; kc < 8; kc++) {
#pragma unroll
                for (int nt = 0; nt < 8; nt++) {
                    uint32_t bf[2];
                    const uint32_t* bb = Ku + (nt * 8 + r) * 68 + kc * 8 + q;
                    bf[0] = bb[0];
                    bf[1] = bb[4];
                    mma_tf32(sf[nt], qf[kc], bf);
                }
            }
        }

        // online softmax
        float rm0 = -1e30f, rm1 = -1e30f;
#pragma unroll
        for (int nt = 0; nt < 8; nt++) {
            rm0 = fmaxf(rm0, fmaxf(sf[nt][0], sf[nt][1]));
            rm1 = fmaxf(rm1, fmaxf(sf[nt][2], sf[nt][3]));
        }
        rm0 = fmaxf(rm0, __shfl_xor_sync(0xffffffffu, rm0, 1));
        rm0 = fmaxf(rm0, __shfl_xor_sync(0xffffffffu, rm0, 2));
        rm1 = fmaxf(rm1, __shfl_xor_sync(0xffffffffu, rm1, 1));
        rm1 = fmaxf(rm1, __shfl_xor_sync(0xffffffffu, rm1, 2));
        const float mn0 = fmaxf(m0v, rm0);
        const float mn1 = fmaxf(m1v, rm1);
        const float corr0 = fexp2(m0v - mn0);
        const float corr1 = fexp2(m1v - mn1);
        float rs0 = 0.f, rs1 = 0.f;
#pragma unroll
        for (int nt = 0; nt < 8; nt++) {
            float p0 = fexp2(sf[nt][0] - mn0);
            float p1 = fexp2(sf[nt][1] - mn0);
            float p2 = fexp2(sf[nt][2] - mn1);
            float p3 = fexp2(sf[nt][3] - mn1);
            rs0 += p0 + p1;
            rs1 += p2 + p3;
            uint2 w0 = {cvt_tf32(p0), cvt_tf32(p1)};
            uint2 w1 = {cvt_tf32(p2), cvt_tf32(p3)};
            *(uint2*)(Pu + r * 68 + nt * 8 + 2 * q) = w0;
            *(uint2*)(Pu + (r + 8) * 68 + nt * 8 + 2 * q) = w1;
        }
        rs0 += __shfl_xor_sync(0xffffffffu, rs0, 1);
        rs0 += __shfl_xor_sync(0xffffffffu, rs0, 2);
        rs1 += __shfl_xor_sync(0xffffffffu, rs1, 1);
        rs1 += __shfl_xor_sync(0xffffffffu, rs1, 2);
        l0 = l0 * corr0 + rs0;
        l1 = l1 * corr1 + rs1;
        m0v = mn0;
        m1v = mn1;
#pragma unroll
        for (int nt = 0; nt < 8; nt++) {
            of[nt][0] *= corr0; of[nt][1] *= corr0;
            of[nt][2] *= corr1; of[nt][3] *= corr1;
        }
        __syncwarp();

        // O += P V (V transposed -> conflict-free B frags)
        {
            const uint32_t* Vu = (const uint32_t*)Vs;
#pragma unroll
            for (int kc = 0; kc < 8; kc++) {
                uint32_t af[4];
                const uint32_t* ab = Pu + r * 68 + kc * 8 + q;
                af[0] = ab[0];
                af[1] = ab[8 * 68];
                af[2] = ab[4];
                af[3] = ab[8 * 68 + 4];
#pragma unroll
                for (int nt = 0; nt < 8; nt++) {
                    uint32_t bf[2];
                    const uint32_t* bb = Vu + (nt * 8 + r) * 68 + kc * 8 + q;
                    bf[0] = bb[0];
                    bf[1] = bb[4];
                    mma_tf32(of[nt], af, bf);
                }
            }
        }
        __syncthreads();   // protect Vs / Pu before next iteration
    }

    // normalize + store (rounded: feeds proj GEMM)
    const float inv0 = 1.0f / l0;
    const float inv1 = 1.0f / l1;
    const int row0 = q0 + wid * 16 + r;
#pragma unroll
    for (int nt = 0; nt < 8; nt++) {
        const int col = h * HD + nt * 8 + 2 * q;
        float2 w0 = {round_tf32f(of[nt][0] * inv0), round_tf32f(of[nt][1] * inv0)};
        float2 w1 = {round_tf32f(of[nt][2] * inv1), round_tf32f(of[nt][3] * inv1)};
        *(float2*)(out + (long)row0 * CDIM + col) = w0;
        *(float2*)(out + (long)(row0 + 8) * CDIM + col) = w1;
    }
}

// ---------------- launch -----------------------------------------------------
extern "C" void kernel_launch(void* const* d_in, const int* in_sizes, int n_in,
                              void* d_out, int out_size)
{
    const float* x      = (const float*)d_in[0];
    const float* cos_t  = (const float*)d_in[1];
    const float* sin_t  = (const float*)d_in[2];
    const float* w_qkv  = (const float*)d_in[3];
    const float* w_proj = (const float*)d_in[4];
    const float* b_proj = (const float*)d_in[5];
    const float* g1     = (const float*)d_in[6];
    const float* beta1  = (const float*)d_in[7];
    const float* g2     = (const float*)d_in[8];
    const float* beta2  = (const float*)d_in[9];
    const float* w_fc1  = (const float*)d_in[10];
    const float* b_fc1  = (const float*)d_in[11];
    const float* w_fc2  = (const float*)d_in[12];
    const float* b_fc2  = (const float*)d_in[13];
    float* out = (float*)d_out;

    float *h, *qkv, *o, *x1, *fc1, *wq, *wp, *w1, *w2;
    cudaGetSymbolAddress((void**)&h,   g_h);
    cudaGetSymbolAddress((void**)&qkv, g_qkv);
    cudaGetSymbolAddress((void**)&o,   g_o);
    cudaGetSymbolAddress((void**)&x1,  g_x1);
    cudaGetSymbolAddress((void**)&fc1, g_fc1);
    cudaGetSymbolAddress((void**)&wq,  g_wq);
    cudaGetSymbolAddress((void**)&wp,  g_wp);
    cudaGetSymbolAddress((void**)&w1,  g_w1);
    cudaGetSymbolAddress((void**)&w2,  g_w2);

    const int GEMM_SMEM = 2 * GSTAGE * 4;           // 73728
    const int ATTN_SMEM = (3 * 64 + 128) * 68 * 4;  // 87040
    cudaFuncSetAttribute(gemm_cp<false, false, false, true>,
                         cudaFuncAttributeMaxDynamicSharedMemorySize, GEMM_SMEM);
    cudaFuncSetAttribute(gemm_cp<true, true, false, false>,
                         cudaFuncAttributeMaxDynamicSharedMemorySize, GEMM_SMEM);
    cudaFuncSetAttribute(gemm_cp<true, false, true, true>,
                         cudaFuncAttributeMaxDynamicSharedMemorySize, GEMM_SMEM);
    cudaFuncSetAttribute(attn_mma,
                         cudaFuncAttributeMaxDynamicSharedMemorySize, ATTN_SMEM);

    // 0. round weights once (~20us)
    round_kernel<<<QKVD * CDIM / 1024, 256>>>(w_qkv, wq);
    round_kernel<<<CDIM * CDIM / 1024, 256>>>(w_proj, wp);
    round_kernel<<<FF * CDIM / 1024, 256>>>(w_fc1, w1);
    round_kernel<<<CDIM * FF / 1024, 256>>>(w_fc2, w2);

    // 1. h = LN1(x)  (rounded)
    ln_kernel<<<NTOK, 256>>>(x, g1, beta1, h);
    // 2. qkv = h @ wq^T  (rounded output)
    gemm_cp<false, false, false, true><<<dim3(QKVD / 128, NTOK / 128), 256, GEMM_SMEM>>>(
        h, wq, nullptr, nullptr, qkv, NTOK, QKVD, CDIM);
    // 3. RoPE(q, k)  (q scaled by 1/8*log2e, both rounded)
    rope_kernel<<<(NTOK * NH * 32 + 255) / 256, 256>>>(qkv, cos_t, sin_t);
    // 4. o = attention(q, k, v)  (rounded output)
    attn_mma<<<dim3(NTOK / 128, NH), 256, ATTN_SMEM>>>(qkv, o);
    // 5. x1 = x + o @ wp^T + b_proj
    gemm_cp<true, true, false, false><<<dim3(CDIM / 128, NTOK / 128), 256, GEMM_SMEM>>>(
        o, wp, b_proj, x, x1, NTOK, CDIM, CDIM);
    // 6. h = LN2(x1)  (rounded)
    ln_kernel<<<NTOK, 256>>>(x1, g2, beta2, h);
    // 7. fc1 = gelu(h @ w1^T + b_fc1)  (rounded output)
    gemm_cp<true, false, true, true><<<dim3(FF / 128, NTOK / 128), 256, GEMM_SMEM>>>(
        h, w1, b_fc1, nullptr, fc1, NTOK, FF, CDIM);
    // 8. out = x1 + fc1 @ w2^T + b_fc2
    gemm_cp<true, true, false, false><<<dim3(CDIM / 128, NTOK / 128), 256, GEMM_SMEM>>>(
        fc1, w2, b_fc2, x1, out, NTOK, CDIM, FF);
}